// round 17
// baseline (speedup 1.0000x reference)
#include <cuda_runtime.h>
#include <cuda_bf16.h>
#include <cuda_fp16.h>

// ---------------- problem constants ----------------
#define NC 96          // B*C = 32*3
#define S0 510
#define S1 258         // (510+7)/2
#define S2 132         // (258+7)/2

// ---------------- static scratch ----------------
__device__ __half  g_a1 [NC * S1 * S1];  // a1  (dwt1 out -> dwt2 in), fp16
__device__ __half  g_a1r[NC * S1 * S1];  // a1r (idwt2 out -> idwt1 in), fp16
__device__ __half2 g_hv1[NC * S1 * S1];  // level-1 (h,v) packed, fp16
__device__ __half  g_d1 [NC * S1 * S1];  // level-1 d plane, fp16
__device__ float4  g_p2 [NC * S2 * S2];  // level-2 packed (x=a, y=h, z=v, w=d), fp32
__device__ float   g_max[6 * NC];        // bands: 0..2 = h1,v1,d1 ; 3..5 = h2,v2,d2

// db4 filters as compile-time constants (FFMA-imm; round-16 win).
__device__ __forceinline__ constexpr float CLOf(int t) {
    return (t == 0) ?  0.23037781330885523f
         : (t == 1) ?  0.7148465705525415f
         : (t == 2) ?  0.6308807679295904f
         : (t == 3) ? -0.02798376941698385f
         : (t == 4) ? -0.18703481171888114f
         : (t == 5) ?  0.030841381835986965f
         : (t == 6) ?  0.032883011666982945f
         :            -0.010597401784997278f;
}
__device__ __forceinline__ constexpr float CHIf(int t) {
    return (t == 0) ? -0.010597401784997278f
         : (t == 1) ? -0.032883011666982945f
         : (t == 2) ?  0.030841381835986965f
         : (t == 3) ?  0.18703481171888114f
         : (t == 4) ? -0.02798376941698385f
         : (t == 5) ? -0.6308807679295904f
         : (t == 6) ?  0.7148465705525415f
         :            -0.23037781330885523f;
}

__device__ __forceinline__ int reflect(int idx, int S) {
    if (idx < 0)  return -1 - idx;
    if (idx >= S) return 2 * S - 1 - idx;
    return idx;
}

__device__ __forceinline__ float soft(float x, float t) {
    return copysignf(fmaxf(fabsf(x) * 1.5f - t, 0.f), x);
}

__device__ __forceinline__ float ld_as_float(const float* p)  { return *p; }
__device__ __forceinline__ float ld_as_float(const __half* p) { return __half2float(*p); }
__device__ __forceinline__ float2 ld2_as_float2(const float* p)  { return *(const float2*)p; }
__device__ __forceinline__ float2 ld2_as_float2(const __half* p) { return __half22float2(*(const __half2*)p); }

// One synthesis row-pair: window (a0..a3) of lo, (b0..b3) of hi -> even/odd outputs.
__device__ __forceinline__ void row_pair(
        float a0, float a1, float a2, float a3,
        float b0, float b1, float b2, float b3,
        float& e, float& o) {
    e = fmaf(a0, CLOf(6), fmaf(a1, CLOf(4), fmaf(a2, CLOf(2), fmaf(a3, CLOf(0),
        fmaf(b0, CHIf(6), fmaf(b1, CHIf(4), fmaf(b2, CHIf(2), b3 * CHIf(0))))))));
    o = fmaf(a0, CLOf(7), fmaf(a1, CLOf(5), fmaf(a2, CLOf(3), fmaf(a3, CLOf(1),
        fmaf(b0, CHIf(7), fmaf(b1, CHIf(5), fmaf(b2, CHIf(3), b3 * CHIf(1))))))));
}

// ================= analysis: full-width strip, column DWT in registers =====
// Band mapping (fixed round 5): h-band <- rowLO(colHI)=vv ; v-band <- rowHI(colLO)=vh.
template<int H, int W, int Hc, int Wc, int BB, int BLK, bool LEVEL1, bool PAIRED,
         typename InT>
__global__ void __launch_bounds__(BLK) dwt2_strip(
        const InT* __restrict__ x,
        __half* __restrict__ aplane, __half2* __restrict__ hvplane,
        __half* __restrict__ dplane, float4* __restrict__ packed) {
    constexpr int TKH = 8;
    constexpr int RN  = 2 * TKH + 6;   // 22 input rows per strip
    constexpr int WPAD = W + 12;       // 6 halo each side (even)
    constexpr int NW  = BLK / 32;
    constexpr int WPR = (NW >= TKH) ? NW / TKH : 1;
    static_assert(NW >= TKH, "phase B needs >= TKH warps");
    __shared__ __align__(16) float sclo[TKH][WPAD];
    __shared__ __align__(16) float schi[TKH][WPAD];

    const int kh0 = blockIdx.x * TKH;
    const int nc  = blockIdx.y;
    const int tid = threadIdx.x;
    const InT* xp = x + (size_t)nc * H * W;
    const int r0 = 2 * kh0 - 6;

    // Phase A: column DWT.
    if constexpr (PAIRED) {
        for (int p = tid; p < W / 2; p += BLK) {
            const int c = 2 * p;
            float2 xv[RN];
#pragma unroll
            for (int rr = 0; rr < RN; rr++) {
                int r = reflect(r0 + rr, H);
                xv[rr] = ld2_as_float2(&xp[(size_t)r * W + c]);
            }
#pragma unroll
            for (int khl = 0; khl < TKH; khl++) {
                float al0 = 0.f, ah0 = 0.f, al1 = 0.f, ah1 = 0.f;
#pragma unroll
                for (int t = 0; t < 8; t++) {
                    float2 v = xv[2 * khl + t];
                    al0 = fmaf(v.x, CLOf(t), al0);
                    ah0 = fmaf(v.x, CHIf(t), ah0);
                    al1 = fmaf(v.y, CLOf(t), al1);
                    ah1 = fmaf(v.y, CHIf(t), ah1);
                }
                *(float2*)&sclo[khl][6 + c] = make_float2(al0, al1);
                *(float2*)&schi[khl][6 + c] = make_float2(ah0, ah1);
            }
        }
    } else {
        for (int c = tid; c < W; c += BLK) {
            float xv[RN];
#pragma unroll
            for (int rr = 0; rr < RN; rr++) {
                int r = reflect(r0 + rr, H);
                xv[rr] = ld_as_float(&xp[(size_t)r * W + c]);
            }
#pragma unroll
            for (int khl = 0; khl < TKH; khl++) {
                float al = 0.f, ah = 0.f;
#pragma unroll
                for (int t = 0; t < 8; t++) {
                    float v = xv[2 * khl + t];
                    al = fmaf(v, CLOf(t), al);
                    ah = fmaf(v, CHIf(t), ah);
                }
                sclo[khl][6 + c] = al;
                schi[khl][6 + c] = ah;
            }
        }
    }
    __syncthreads();

    // Halo fill: horizontal reflection commutes with the column transform.
    if (tid < 12 * TKH) {
        int hc = tid % 12, khl = tid / 12;
        int c   = (hc < 6) ? hc - 6 : W + (hc - 6);
        int src = (c < 0) ? -1 - c : 2 * W - 1 - c;
        sclo[khl][6 + c] = sclo[khl][6 + src];
        schi[khl][6 + c] = schi[khl][6 + src];
    }
    __syncthreads();

    // Phase B: row DWT; 2 coefficients per thread, vector stores.
    const int wid = tid >> 5, lane = tid & 31;
    const int row = wid / WPR, sub = wid % WPR;
    float m_h = 0.f, m_v = 0.f, m_d = 0.f;
    if (row < TKH) {
        const int kh = kh0 + row;
        if (kh < Hc) {
            const float2* plo = (const float2*)(&sclo[row][0]);
            const float2* phi = (const float2*)(&schi[row][0]);
            const unsigned ob = ((unsigned)nc * Hc + kh) * Wc;
            for (int k2 = lane + 32 * sub; k2 < Wc / 2; k2 += 32 * WPR) {
                const int k = 2 * k2;
                float2 l0 = plo[k],     l1 = plo[k + 1], l2 = plo[k + 2];
                float2 l3 = plo[k + 3], l4 = plo[k + 4];
                float2 h0 = phi[k],     h1 = phi[k + 1], h2 = phi[k + 2];
                float2 h3 = phi[k + 3], h4 = phi[k + 4];
                float va0, vh0, vv0, vd0, va1, vh1, vv1, vd1;
                va0 = fmaf(l0.x, CLOf(0), fmaf(l0.y, CLOf(1), fmaf(l1.x, CLOf(2), fmaf(l1.y, CLOf(3),
                      fmaf(l2.x, CLOf(4), fmaf(l2.y, CLOf(5), fmaf(l3.x, CLOf(6), l3.y * CLOf(7))))))));
                vh0 = fmaf(l0.x, CHIf(0), fmaf(l0.y, CHIf(1), fmaf(l1.x, CHIf(2), fmaf(l1.y, CHIf(3),
                      fmaf(l2.x, CHIf(4), fmaf(l2.y, CHIf(5), fmaf(l3.x, CHIf(6), l3.y * CHIf(7))))))));
                vv0 = fmaf(h0.x, CLOf(0), fmaf(h0.y, CLOf(1), fmaf(h1.x, CLOf(2), fmaf(h1.y, CLOf(3),
                      fmaf(h2.x, CLOf(4), fmaf(h2.y, CLOf(5), fmaf(h3.x, CLOf(6), h3.y * CLOf(7))))))));
                vd0 = fmaf(h0.x, CHIf(0), fmaf(h0.y, CHIf(1), fmaf(h1.x, CHIf(2), fmaf(h1.y, CHIf(3),
                      fmaf(h2.x, CHIf(4), fmaf(h2.y, CHIf(5), fmaf(h3.x, CHIf(6), h3.y * CHIf(7))))))));
                va1 = fmaf(l1.x, CLOf(0), fmaf(l1.y, CLOf(1), fmaf(l2.x, CLOf(2), fmaf(l2.y, CLOf(3),
                      fmaf(l3.x, CLOf(4), fmaf(l3.y, CLOf(5), fmaf(l4.x, CLOf(6), l4.y * CLOf(7))))))));
                vh1 = fmaf(l1.x, CHIf(0), fmaf(l1.y, CHIf(1), fmaf(l2.x, CHIf(2), fmaf(l2.y, CHIf(3),
                      fmaf(l3.x, CHIf(4), fmaf(l3.y, CHIf(5), fmaf(l4.x, CHIf(6), l4.y * CHIf(7))))))));
                vv1 = fmaf(h1.x, CLOf(0), fmaf(h1.y, CLOf(1), fmaf(h2.x, CLOf(2), fmaf(h2.y, CLOf(3),
                      fmaf(h3.x, CLOf(4), fmaf(h3.y, CLOf(5), fmaf(h4.x, CLOf(6), h4.y * CLOf(7))))))));
                vd1 = fmaf(h1.x, CHIf(0), fmaf(h1.y, CHIf(1), fmaf(h2.x, CHIf(2), fmaf(h2.y, CHIf(3),
                      fmaf(h3.x, CHIf(4), fmaf(h3.y, CHIf(5), fmaf(h4.x, CHIf(6), h4.y * CHIf(7))))))));
                if constexpr (LEVEL1) {
                    *(__half2*)&aplane[ob + k] = __floats2half2_rn(va0, va1);
                    __half2 p0 = __floats2half2_rn(vv0, vh0);
                    __half2 p1 = __floats2half2_rn(vv1, vh1);
                    uint2 hv2;
                    hv2.x = *(unsigned*)&p0;
                    hv2.y = *(unsigned*)&p1;
                    *(uint2*)&hvplane[ob + k] = hv2;
                    *(__half2*)&dplane[ob + k] = __floats2half2_rn(vd0, vd1);
                } else {
                    packed[ob + k]     = make_float4(va0, vv0, vh0, vd0);
                    packed[ob + k + 1] = make_float4(va1, vv1, vh1, vd1);
                }
                m_h = fmaxf(m_h, fmaxf(fabsf(vv0), fabsf(vv1)));
                m_v = fmaxf(m_v, fmaxf(fabsf(vh0), fabsf(vh1)));
                m_d = fmaxf(m_d, fmaxf(fabsf(vd0), fabsf(vd1)));
            }
        }
    }

#pragma unroll
    for (int o = 16; o > 0; o >>= 1) {
        m_h = fmaxf(m_h, __shfl_xor_sync(0xffffffffu, m_h, o));
        m_v = fmaxf(m_v, __shfl_xor_sync(0xffffffffu, m_v, o));
        m_d = fmaxf(m_d, __shfl_xor_sync(0xffffffffu, m_d, o));
    }
    __shared__ float rmax[NW][3];
    if (lane == 0) { rmax[wid][0] = m_h; rmax[wid][1] = m_v; rmax[wid][2] = m_d; }
    __syncthreads();
    if (tid < 3) {
        float m = rmax[0][tid];
#pragma unroll
        for (int i = 1; i < NW; i++) m = fmaxf(m, rmax[i][tid]);
        atomicMax((int*)&g_max[(BB + tid) * NC + nc], __float_as_int(m));
    }
}

// ================= synthesis: sub-strip + width-split, column IDWT =========
// PA=true : bands from P4 = (a,h,v,d) fp32; output OutT (fp16 a1r).
// PA=false: HV (half2), D (half), A (fp16 a1r); output fp32 (final).
// Phase B: 4 pairs (8 pixels) per thread via 2x LDS.128 per band row.
template<int Hc, int Wc, int H, int W, int BB, int BLK, bool PA,
         int TM, int PR, int TWB, typename OutT>
__global__ void __launch_bounds__(BLK) idwt2_strip(
        const float4* __restrict__ P4,  const __half2* __restrict__ HV,
        const __half* __restrict__ Dp,  const __half* __restrict__ Ap,
        OutT* __restrict__ outd) {
    constexpr int RWH = PR + 3;                    // coeff rows per group
    constexpr int NG  = (TM / 2) / PR;             // groups
    constexpr int CC  = (TWB / 2 + 3 < Wc) ? TWB / 2 + 3 : Wc;  // logical coeff cols
    constexpr int CCP = (CC + 3) & ~3;             // row stride mult of 4 (LDS.128)
    constexpr int NW  = BLK / 32;
    static_assert((CCP * 4) % 16 == 0, "row stride must be 16B multiple");
    __shared__ __align__(16) float slo[TM][CCP];
    __shared__ __align__(16) float shi[TM][CCP];

    const int w0  = blockIdx.x * TWB;
    const int c0  = w0 >> 1;
    const int m0  = blockIdx.y * TM;
    const int nc  = blockIdx.z;
    const int tid = threadIdx.x;
    const float th = 0.3f * g_max[(BB + 0) * NC + nc];
    const float tv = 0.3f * g_max[(BB + 1) * NC + nc];
    const float td = 0.3f * g_max[(BB + 2) * NC + nc];

    // Phase A: NG*CC active threads; one independent vector-load batch each.
    if (tid < NG * CC) {
        const int g  = tid / CC;
        const int j  = tid - g * CC;
        const int pb = g * PR;
        const int qs = (m0 >> 1) + pb;
        const int cg = min(c0 + j, Wc - 1);        // clamped col feeds only masked outputs
        const size_t cb = (size_t)nc * Hc * Wc;

        float Aw[RWH], Hw[RWH], Vw[RWH], Dw[RWH];
        if constexpr (PA) {
            float4 Cw[RWH];
#pragma unroll
            for (int i = 0; i < RWH; i++) {
                int q = min(qs + i, Hc - 1);
                Cw[i] = P4[cb + (unsigned)q * Wc + cg];
            }
#pragma unroll
            for (int i = 0; i < RWH; i++) {
                Aw[i] = Cw[i].x;
                Hw[i] = soft(Cw[i].y, th);
                Vw[i] = soft(Cw[i].z, tv);
                Dw[i] = soft(Cw[i].w, td);
            }
        } else {
            __half2 hv[RWH]; __half dv[RWH], av[RWH];
#pragma unroll
            for (int i = 0; i < RWH; i++) {
                int q = min(qs + i, Hc - 1);
                size_t o = cb + (unsigned)q * Wc + cg;
                hv[i] = HV[o];
                dv[i] = Dp[o];
                av[i] = Ap[o];
            }
#pragma unroll
            for (int i = 0; i < RWH; i++) {
                float2 f = __half22float2(hv[i]);
                Aw[i] = __half2float(av[i]);
                Hw[i] = soft(f.x, th);
                Vw[i] = soft(f.y, tv);
                Dw[i] = soft(__half2float(dv[i]), td);
            }
        }
#pragma unroll
        for (int pp = 0; pp < PR; pp++) {
            const int ml = 2 * (pb + pp);
            float e_lo = 0.f, o_lo = 0.f, e_hi = 0.f, o_hi = 0.f;
#pragma unroll
            for (int i = 0; i < 4; i++) {
                e_lo = fmaf(Aw[pp + i], CLOf(6 - 2 * i), fmaf(Hw[pp + i], CHIf(6 - 2 * i), e_lo));
                o_lo = fmaf(Aw[pp + i], CLOf(7 - 2 * i), fmaf(Hw[pp + i], CHIf(7 - 2 * i), o_lo));
                e_hi = fmaf(Vw[pp + i], CLOf(6 - 2 * i), fmaf(Dw[pp + i], CHIf(6 - 2 * i), e_hi));
                o_hi = fmaf(Vw[pp + i], CLOf(7 - 2 * i), fmaf(Dw[pp + i], CHIf(7 - 2 * i), o_hi));
            }
            slo[ml][j]     = e_lo;
            slo[ml + 1][j] = o_lo;
            shi[ml][j]     = e_hi;
            shi[ml + 1][j] = o_hi;
        }
    }
    __syncthreads();

    // Phase B: row IDWT; 4 pairs (8 pixels) per thread, LDS.128 window loads.
    const int wid = tid >> 5, lane = tid & 31;
    const int we  = (w0 + TWB < W) ? w0 + TWB : W;
    const int NPb = (we - w0) >> 1;                // output pairs in this block
    const int NPQ = (NPb + 3) >> 2;                // 4-pair groups
    for (int rr = wid; rr < TM; rr += NW) {
        int m = m0 + rr;
        if (m >= H) break;
        OutT* od = outd + (size_t)nc * H * W + (size_t)m * W + w0;
        for (int q4 = lane; q4 < NPQ; q4 += 32) {
            const int wp = 4 * q4;
            float4 lA = *(const float4*)&slo[rr][wp];
            float4 hA = *(const float4*)&shi[rr][wp];
            float4 lB, hB;
            if (wp + 7 < CCP) {
                lB = *(const float4*)&slo[rr][wp + 4];
                hB = *(const float4*)&shi[rr][wp + 4];
            } else {
                lB = make_float4(0.f, 0.f, 0.f, 0.f);
                hB = make_float4(0.f, 0.f, 0.f, 0.f);
            }
            float e, o;
            // pair wp+0: window lA.x..lA.w
            row_pair(lA.x, lA.y, lA.z, lA.w, hA.x, hA.y, hA.z, hA.w, e, o);
            if constexpr (sizeof(OutT) == 2) *(__half2*)&od[2 * wp] = __floats2half2_rn(e, o);
            else                             *(float2*)&od[2 * wp] = make_float2(e, o);
            // pair wp+1
            if (wp + 1 < NPb) {
                row_pair(lA.y, lA.z, lA.w, lB.x, hA.y, hA.z, hA.w, hB.x, e, o);
                if constexpr (sizeof(OutT) == 2) *(__half2*)&od[2 * wp + 2] = __floats2half2_rn(e, o);
                else                             *(float2*)&od[2 * wp + 2] = make_float2(e, o);
            }
            // pair wp+2
            if (wp + 2 < NPb) {
                row_pair(lA.z, lA.w, lB.x, lB.y, hA.z, hA.w, hB.x, hB.y, e, o);
                if constexpr (sizeof(OutT) == 2) *(__half2*)&od[2 * wp + 4] = __floats2half2_rn(e, o);
                else                             *(float2*)&od[2 * wp + 4] = make_float2(e, o);
            }
            // pair wp+3
            if (wp + 3 < NPb) {
                row_pair(lA.w, lB.x, lB.y, lB.z, hA.w, hB.x, hB.y, hB.z, e, o);
                if constexpr (sizeof(OutT) == 2) *(__half2*)&od[2 * wp + 6] = __floats2half2_rn(e, o);
                else                             *(float2*)&od[2 * wp + 6] = make_float2(e, o);
            }
        }
    }
}

// ---------------- host ----------------
static inline unsigned cdiv(unsigned a, unsigned b) { return (a + b - 1) / b; }

extern "C" void kernel_launch(void* const* d_in, const int* in_sizes, int n_in,
                              void* d_out, int out_size) {
    (void)in_sizes; (void)n_in; (void)out_size;
    const float* x = (const float*)d_in[0];
    float* out = (float*)d_out;

    __half  *a1, *a1r, *d1;
    __half2 *hv1;
    float4  *p2;
    float   *gmax;
    cudaGetSymbolAddress((void**)&a1,   g_a1);
    cudaGetSymbolAddress((void**)&a1r,  g_a1r);
    cudaGetSymbolAddress((void**)&d1,   g_d1);
    cudaGetSymbolAddress((void**)&hv1,  g_hv1);
    cudaGetSymbolAddress((void**)&p2,   g_p2);
    cudaGetSymbolAddress((void**)&gmax, g_max);

    // Zero the band maxima via a captured memset node.
    cudaMemsetAsync(gmax, 0, 6 * NC * sizeof(float));

    // Level-1 analysis: x (fp32) -> a1/hv1/d1 (fp16).  PAIRED phase A, 256 thr.
    dwt2_strip<S0, S0, S1, S1, 0, 256, true, true, float>
        <<<dim3(cdiv(S1, 8), NC), 256>>>(x, a1, hv1, d1, nullptr);

    // Level-2 analysis: a1 (fp16) -> p2 (fp32).  Single-column phase A, 288 thr.
    dwt2_strip<S1, S1, S2, S2, 3, 288, false, false, __half>
        <<<dim3(cdiv(S2, 8), NC), 288>>>(a1, nullptr, nullptr, nullptr, p2);

    // Level-2 synthesis: p2 -> a1r (fp16).  TM=16, PR=4, no split.
    idwt2_strip<S2, S2, S1, S1, 3, 288, true, 16, 4, S1, __half>
        <<<dim3(1, cdiv(S1, 16), NC), 288>>>(p2, nullptr, nullptr, nullptr, a1r);

    // Level-1 synthesis: (a1r/hv1/d1 fp16) -> out (fp32).  TM=16, PR=4, split x2.
    idwt2_strip<S1, S1, S0, S0, 0, 288, false, 16, 4, 256, float>
        <<<dim3(2, cdiv(S0, 16), NC), 288>>>(nullptr, hv1, d1, a1r, out);
}